// round 4
// baseline (speedup 1.0000x reference)
#include <cuda_runtime.h>
#include <math.h>

// Problem constants
#define B_   2
#define S_   2048
#define D_   1024
#define H_   16
#define DK_  64
#define M_   (B_*S_)     // 4096
#define NQKV (3*D_)      // 3072

// Scratch (device globals — no allocation allowed)
__device__ float  g_Q[B_*H_*S_*DK_];
__device__ float  g_K[B_*H_*S_*DK_];
__device__ float  g_V[B_*H_*S_*DK_];
__device__ float  g_attn[(size_t)M_*D_];
__device__ float  g_xr[(size_t)M_*D_];        // tf32-rounded x
__device__ float  g_wqkvr[(size_t)NQKV*D_];   // tf32-rounded W_qkv
__device__ float  g_wor[(size_t)D_*D_];       // tf32-rounded W_o
__device__ float2 g_rope[2048*32];            // [pos][pair] = (cos, sin)

// ---------------- helpers ----------------
__device__ __forceinline__ unsigned f2tf(float x) {
    unsigned u;
    asm("cvt.rna.tf32.f32 %0, %1;" : "=r"(u) : "f"(x));
    return u;
}
__device__ __forceinline__ float tfbits(float x) { return __uint_as_float(f2tf(x)); }

__device__ __forceinline__ void mma_tf32(float* c, const unsigned* a, const unsigned* b) {
    asm volatile(
        "mma.sync.aligned.m16n8k8.row.col.f32.tf32.tf32.f32 "
        "{%0,%1,%2,%3}, {%4,%5,%6,%7}, {%8,%9}, {%0,%1,%2,%3};\n"
        : "+f"(c[0]), "+f"(c[1]), "+f"(c[2]), "+f"(c[3])
        : "r"(a[0]), "r"(a[1]), "r"(a[2]), "r"(a[3]),
          "r"(b[0]), "r"(b[1]));
}

__device__ __forceinline__ void cp16(unsigned saddr, const void* gaddr) {
    asm volatile("cp.async.cg.shared.global [%0], [%1], 16;\n" :: "r"(saddr), "l"(gaddr));
}
__device__ __forceinline__ void cp_commit() { asm volatile("cp.async.commit_group;\n"); }
template<int N> __device__ __forceinline__ void cp_wait() {
    asm volatile("cp.async.wait_group %0;\n" :: "n"(N));
}

// ---------------- pre-round to tf32 ----------------
__global__ void round_kernel(const float4* __restrict__ s, float4* __restrict__ d, int n4) {
    int i = blockIdx.x * 256 + threadIdx.x;
    if (i < n4) {
        float4 v = s[i];
        d[i] = make_float4(tfbits(v.x), tfbits(v.y), tfbits(v.z), tfbits(v.w));
    }
}

// ---------------- RoPE cos/sin table ----------------
__global__ void rope_tab_kernel() {
    int i = blockIdx.x * 256 + threadIdx.x;     // 0..65535
    int p = i & 31, posv = i >> 5;
    float freq = exp2f(-(float)p * (13.287712379549449f / 32.0f));
    float ang = (float)posv * freq;
    float sn, cs;
    sincosf(ang, &sn, &cs);
    g_rope[i] = make_float2(cs, sn);
}

// ============================================================
// tf32 GEMM: C[m,e] = sum_k A[m,k] * W[e,k]  (K-major, K=1024)
// Block 128x128, BK=16, 3-stage cp.async pipeline.
// 4 warps (2m x 2n), warp tile 64x64 -> LDS:MMA ratio 1.0.
// ============================================================
#define LDA 20         // smem row stride (floats)
#define STGF (128*LDA) // floats per stage per matrix = 2560

__device__ __forceinline__ void gemm_load_stage(
    float* Asb, float* Bsb, const float* A, const float* W,
    int m0, int n0, int k0, int tid)
{
    // 128 threads: thread t loads row t of A (64B) and row t of B (64B)
    unsigned sa = (unsigned)__cvta_generic_to_shared(Asb + tid*LDA);
    unsigned sb = (unsigned)__cvta_generic_to_shared(Bsb + tid*LDA);
    const float* ga = A + (size_t)(m0 + tid)*1024 + k0;
    const float* gb = W + (size_t)(n0 + tid)*1024 + k0;
    #pragma unroll
    for (int c = 0; c < 4; c++) {
        cp16(sa + c*16, ga + c*4);
        cp16(sb + c*16, gb + c*4);
    }
}

template<bool ROPE>
__global__ __launch_bounds__(128)
void gemm_tf32(const float* __restrict__ Ain, const float* __restrict__ W,
               const int* __restrict__ pos, float* __restrict__ Cout)
{
    extern __shared__ float dsm[];
    float* As = dsm;             // 3 stages x 2560
    float* Bs = dsm + 3*STGF;

    const float* A = ROPE ? Ain : (const float*)g_attn;

    const int tid = threadIdx.x, lane = tid & 31, wrp = tid >> 5;
    const int wm = wrp >> 1, wn = wrp & 1;
    const int g  = lane >> 2, tg = lane & 3;
    const int m0 = blockIdx.y * 128, n0 = blockIdx.x * 128;

    float acc[4][8][4];
    #pragma unroll
    for (int i = 0; i < 4; i++)
        #pragma unroll
        for (int j = 0; j < 8; j++)
            #pragma unroll
            for (int k = 0; k < 4; k++) acc[i][j][k] = 0.f;

    gemm_load_stage(As,        Bs,        A, W, m0, n0, 0,  tid); cp_commit();
    gemm_load_stage(As + STGF, Bs + STGF, A, W, m0, n0, 16, tid); cp_commit();

    for (int kt = 0; kt < 64; kt++) {
        cp_wait<1>();
        __syncthreads();
        if (kt + 2 < 64) {
            int s = (kt + 2) % 3;
            gemm_load_stage(As + s*STGF, Bs + s*STGF, A, W, m0, n0, (kt + 2)*16, tid);
        }
        cp_commit();

        const float* as = As + (kt % 3)*STGF;
        const float* bs = Bs + (kt % 3)*STGF;
        #pragma unroll
        for (int ks = 0; ks < 2; ks++) {
            unsigned af[4][4], bf[8][2];
            #pragma unroll
            for (int mt = 0; mt < 4; mt++) {
                int base = (wm*64 + mt*16 + g)*LDA + ks*8 + tg;
                af[mt][0] = __float_as_uint(as[base]);
                af[mt][1] = __float_as_uint(as[base + 8*LDA]);
                af[mt][2] = __float_as_uint(as[base + 4]);
                af[mt][3] = __float_as_uint(as[base + 8*LDA + 4]);
            }
            #pragma unroll
            for (int nt = 0; nt < 8; nt++) {
                int base = (wn*64 + nt*8 + g)*LDA + ks*8 + tg;
                bf[nt][0] = __float_as_uint(bs[base]);
                bf[nt][1] = __float_as_uint(bs[base + 4]);
            }
            #pragma unroll
            for (int mt = 0; mt < 4; mt++)
                #pragma unroll
                for (int nt = 0; nt < 8; nt++)
                    mma_tf32(acc[mt][nt], af[mt], bf[nt]);
        }
    }

    // ---- epilogue ----
    if (ROPE) {
        // warp strip is exactly one head: baseN multiple of 64
        const int baseN = n0 + wn*64;
        const int which = baseN >> 10;              // 0:Q 1:K 2:V
        const int h     = (baseN & 1023) >> 6;
        #pragma unroll
        for (int mt = 0; mt < 4; mt++) {
            int r0 = m0 + wm*64 + mt*16 + g;
            int r1 = r0 + 8;
            int b0i = r0 >> 11, s0 = r0 & 2047;
            int b1i = r1 >> 11, s1 = r1 & 2047;
            if (which == 2) {
                float* d0 = g_V + ((size_t)((b0i*H_ + h)*S_ + s0))*DK_;
                float* d1 = g_V + ((size_t)((b1i*H_ + h)*S_ + s1))*DK_;
                #pragma unroll
                for (int nt = 0; nt < 8; nt++) {
                    int dd = nt*8 + 2*tg;
                    *(float2*)(d0 + dd) = make_float2(tfbits(acc[mt][nt][0]), tfbits(acc[mt][nt][1]));
                    *(float2*)(d1 + dd) = make_float2(tfbits(acc[mt][nt][2]), tfbits(acc[mt][nt][3]));
                }
            } else {
                float* gq = (which == 0) ? g_Q : g_K;
                int p0 = pos[r0], p1 = pos[r1];
                float* d0 = gq + ((size_t)((b0i*H_ + h)*S_ + s0))*DK_;
                float* d1 = gq + ((size_t)((b1i*H_ + h)*S_ + s1))*DK_;
                #pragma unroll
                for (int nt = 0; nt < 8; nt++) {
                    int dd = nt*8 + 2*tg;
                    int p  = nt*4 + tg;
                    float2 cs0 = g_rope[p0*32 + p];
                    float2 cs1 = g_rope[p1*32 + p];
                    float e0 = acc[mt][nt][0], o0 = acc[mt][nt][1];
                    float e1 = acc[mt][nt][2], o1 = acc[mt][nt][3];
                    *(float2*)(d0 + dd) = make_float2(tfbits(cs0.x*e0 - cs0.y*o0), tfbits(cs0.y*e0 + cs0.x*o0));
                    *(float2*)(d1 + dd) = make_float2(tfbits(cs1.x*e1 - cs1.y*o1), tfbits(cs1.y*e1 + cs1.x*o1));
                }
            }
        }
    } else {
        #pragma unroll
        for (int mt = 0; mt < 4; mt++) {
            int r0 = m0 + wm*64 + mt*16 + g;
            #pragma unroll
            for (int nt = 0; nt < 8; nt++) {
                int col = n0 + wn*64 + nt*8 + 2*tg;
                *(float2*)(Cout + (size_t)r0*1024 + col)     = make_float2(acc[mt][nt][0], acc[mt][nt][1]);
                *(float2*)(Cout + (size_t)(r0+8)*1024 + col) = make_float2(acc[mt][nt][2], acc[mt][nt][3]);
            }
        }
    }
}

// ============================================================
// Flash attention, tf32 mma, double-buffered cp.async K/V.
// Block: 128 q-rows, 8 warps (16 rows each). Key tiles of 64.
// ============================================================
#define ABM 128
#define ABN 64
#define KSTR 72             // K/V smem row stride (floats)
#define KVST (ABN*KSTR)     // 4608 floats per matrix per stage

__device__ __forceinline__ void load_kv(float* Kd, float* Vd,
    const float* Kp, const float* Vp, int n0, int tid)
{
    int row = tid >> 2;           // 0..63
    int c0  = (tid & 3) * 4;      // 4 consecutive 16B chunks
    const float* kg = Kp + (size_t)(n0 + row)*DK_ + c0*4;
    const float* vg = Vp + (size_t)(n0 + row)*DK_ + c0*4;
    unsigned ks = (unsigned)__cvta_generic_to_shared(Kd + row*KSTR + c0*4);
    unsigned vs = (unsigned)__cvta_generic_to_shared(Vd + row*KSTR + c0*4);
    #pragma unroll
    for (int c = 0; c < 4; c++) {
        cp16(ks + c*16, kg + c*4);
        cp16(vs + c*16, vg + c*4);
    }
}

__global__ __launch_bounds__(256)
void attn_mma_kernel()
{
    extern __shared__ float dsm[];   // 2 stages x (K 4608 + V 4608) = 18432 floats

    const int tid = threadIdx.x, lane = tid & 31, w = tid >> 5;
    const int g = lane >> 2, tg = lane & 3;
    const int bh = blockIdx.y;
    const int tile = (int)gridDim.x - 1 - (int)blockIdx.x;   // heavy tiles first
    const int m0 = tile * ABM;

    const float* Qp = g_Q + (size_t)bh * S_ * DK_;
    const float* Kp = g_K + (size_t)bh * S_ * DK_;
    const float* Vp = g_V + (size_t)bh * S_ * DK_;

    // ---- stage Q (pre-rounded) into smem, extract A-fragments ----
    for (int f = tid; f < ABM*16; f += 256) {
        int row = f >> 4, q = f & 15;
        *(float4*)&dsm[row*68 + q*4] = *(const float4*)(Qp + (size_t)(m0+row)*DK_ + q*4);
    }
    __syncthreads();

    unsigned qa[8][4];
    {
        int qr = w*16 + g;
        #pragma unroll
        for (int ks = 0; ks < 8; ks++) {
            int base = qr*68 + ks*8 + tg;
            qa[ks][0] = __float_as_uint(dsm[base]);
            qa[ks][1] = __float_as_uint(dsm[base + 8*68]);
            qa[ks][2] = __float_as_uint(dsm[base + 4]);
            qa[ks][3] = __float_as_uint(dsm[base + 8*68 + 4]);
        }
    }
    __syncthreads();

    float o[8][4];
    #pragma unroll
    for (int nt = 0; nt < 8; nt++)
        #pragma unroll
        for (int i = 0; i < 4; i++) o[nt][i] = 0.f;

    float mrow0 = -1e30f, mrow1 = -1e30f, l0 = 0.f, l1 = 0.f;
    const int row0 = m0 + w*16 + g;
    const int row1 = row0 + 8;
    const int fullT = m0 / ABN;
    const int nT = fullT + 2;

    const int src0 = (lane & ~3) | (tg >> 1);
    const int src2 = src0 | 2;
    const bool oddl = tg & 1;

    // pipeline prologue: stage 0
    load_kv(dsm, dsm + KVST, Kp, Vp, 0, tid);
    cp_commit();

    for (int t = 0; t < nT; t++) {
        cp_wait<0>();
        __syncthreads();
        if (t + 1 < nT) {
            float* st = dsm + ((t + 1) & 1) * 2 * KVST;
            load_kv(st, st + KVST, Kp, Vp, (t + 1)*ABN, tid);
            cp_commit();
        }
        const float* Ksm = dsm + (t & 1) * 2 * KVST;
        const float* Vsm = Ksm + KVST;
        const int n0 = t * ABN;

        // ---- scores: S = Q @ K^T ----
        float sc[8][4];
        #pragma unroll
        for (int nt = 0; nt < 8; nt++)
            #pragma unroll
            for (int i = 0; i < 4; i++) sc[nt][i] = 0.f;

        #pragma unroll
        for (int ks = 0; ks < 8; ks++) {
            #pragma unroll
            for (int nt = 0; nt < 8; nt++) {
                unsigned bf[2];
                int base = (nt*8 + g)*KSTR + ks*8 + tg;
                bf[0] = __float_as_uint(Ksm[base]);
                bf[1] = __float_as_uint(Ksm[base + 4]);
                mma_tf32(sc[nt], qa[ks], bf);
            }
        }

        // scale + causal mask
        if (t >= fullT) {
            #pragma unroll
            for (int nt = 0; nt < 8; nt++) {
                int c0 = n0 + nt*8 + 2*tg, c1 = c0 + 1;
                sc[nt][0] = (c0 <= row0) ? sc[nt][0]*0.125f : -1e30f;
                sc[nt][1] = (c1 <= row0) ? sc[nt][1]*0.125f : -1e30f;
                sc[nt][2] = (c0 <= row1) ? sc[nt][2]*0.125f : -1e30f;
                sc[nt][3] = (c1 <= row1) ? sc[nt][3]*0.125f : -1e30f;
            }
        } else {
            #pragma unroll
            for (int nt = 0; nt < 8; nt++)
                #pragma unroll
                for (int i = 0; i < 4; i++) sc[nt][i] *= 0.125f;
        }

        // ---- online softmax (registers + shfl) ----
        float mx0 = -1e30f, mx1 = -1e30f;
        #pragma unroll
        for (int nt = 0; nt < 8; nt++) {
            mx0 = fmaxf(mx0, fmaxf(sc[nt][0], sc[nt][1]));
            mx1 = fmaxf(mx1, fmaxf(sc[nt][2], sc[nt][3]));
        }
        mx0 = fmaxf(mx0, __shfl_xor_sync(0xffffffffu, mx0, 1));
        mx0 = fmaxf(mx0, __shfl_xor_sync(0xffffffffu, mx0, 2));
        mx1 = fmaxf(mx1, __shfl_xor_sync(0xffffffffu, mx1, 1));
        mx1 = fmaxf(mx1, __shfl_xor_sync(0xffffffffu, mx1, 2));

        float mn0 = fmaxf(mrow0, mx0), mn1 = fmaxf(mrow1, mx1);
        float al0 = __expf(mrow0 - mn0), al1 = __expf(mrow1 - mn1);
        mrow0 = mn0; mrow1 = mn1;

        float ls0 = 0.f, ls1 = 0.f;
        #pragma unroll
        for (int nt = 0; nt < 8; nt++) {
            float p0 = __expf(sc[nt][0] - mn0);
            float p1 = __expf(sc[nt][1] - mn0);
            float p2 = __expf(sc[nt][2] - mn1);
            float p3 = __expf(sc[nt][3] - mn1);
            sc[nt][0]=p0; sc[nt][1]=p1; sc[nt][2]=p2; sc[nt][3]=p3;
            ls0 += p0 + p1; ls1 += p2 + p3;
        }
        ls0 += __shfl_xor_sync(0xffffffffu, ls0, 1);
        ls0 += __shfl_xor_sync(0xffffffffu, ls0, 2);
        ls1 += __shfl_xor_sync(0xffffffffu, ls1, 1);
        ls1 += __shfl_xor_sync(0xffffffffu, ls1, 2);
        l0 = l0*al0 + ls0;
        l1 = l1*al1 + ls1;

        #pragma unroll
        for (int nt = 0; nt < 8; nt++) {
            o[nt][0] *= al0; o[nt][1] *= al0;
            o[nt][2] *= al1; o[nt][3] *= al1;
        }

        // ---- PV: O += P @ V ----
        #pragma unroll
        for (int ks = 0; ks < 8; ks++) {
            float v00 = __shfl_sync(0xffffffffu, sc[ks][0], src0);
            float v01 = __shfl_sync(0xffffffffu, sc[ks][1], src0);
            float v10 = __shfl_sync(0xffffffffu, sc[ks][2], src0);
            float v11 = __shfl_sync(0xffffffffu, sc[ks][3], src0);
            float v20 = __shfl_sync(0xffffffffu, sc[ks][0], src2);
            float v21 = __shfl_sync(0xffffffffu, sc[ks][1], src2);
            float v30 = __shfl_sync(0xffffffffu, sc[ks][2], src2);
            float v31 = __shfl_sync(0xffffffffu, sc[ks][3], src2);
            unsigned pa[4];
            pa[0] = f2tf(oddl ? v01 : v00);
            pa[1] = f2tf(oddl ? v11 : v10);
            pa[2] = f2tf(oddl ? v21 : v20);
            pa[3] = f2tf(oddl ? v31 : v30);
            #pragma unroll
            for (int nt = 0; nt < 8; nt++) {
                unsigned bf[2];
                int base = (ks*8 + tg)*KSTR + nt*8 + g;
                bf[0] = __float_as_uint(Vsm[base]);
                bf[1] = __float_as_uint(Vsm[base + 4*KSTR]);
                mma_tf32(o[nt], pa, bf);
            }
        }
    }

    // ---- epilogue: normalize + write tf32-rounded to g_attn ----
    const float il0 = 1.0f / l0, il1 = 1.0f / l1;
    const int bb = bh >> 4, hh = bh & 15;
    float* dst0 = g_attn + ((size_t)(bb*S_ + row0))*D_ + hh*DK_;
    float* dst1 = g_attn + ((size_t)(bb*S_ + row1))*D_ + hh*DK_;
    #pragma unroll
    for (int nt = 0; nt < 8; nt++) {
        int d = nt*8 + 2*tg;
        *(float2*)(dst0 + d) = make_float2(tfbits(o[nt][0]*il0), tfbits(o[nt][1]*il0));
        *(float2*)(dst1 + d) = make_float2(tfbits(o[nt][2]*il1), tfbits(o[nt][3]*il1));
    }
}

// ============================================================
// Launch
// ============================================================
extern "C" void kernel_launch(void* const* d_in, const int* in_sizes, int n_in,
                              void* d_out, int out_size)
{
    const float* x    = (const float*)d_in[0];
    const int*   pos  = (const int*)  d_in[1];
    const float* wqkv = (const float*)d_in[2];
    const float* wo   = (const float*)d_in[3];
    float* out = (float*)d_out;

    (void)in_sizes; (void)n_in; (void)out_size;

    const int GEMM_SMEM = 3*STGF*2*(int)sizeof(float);       // 61440
    const int ATTN_SMEM = 2*2*KVST*(int)sizeof(float);       // 73728
    cudaFuncSetAttribute((const void*)gemm_tf32<true>,
                         cudaFuncAttributeMaxDynamicSharedMemorySize, GEMM_SMEM);
    cudaFuncSetAttribute((const void*)gemm_tf32<false>,
                         cudaFuncAttributeMaxDynamicSharedMemorySize, GEMM_SMEM);
    cudaFuncSetAttribute((const void*)attn_mma_kernel,
                         cudaFuncAttributeMaxDynamicSharedMemorySize, ATTN_SMEM);

    // pre-round inputs to tf32 + rope table
    float* xr; float* wqr; float* wor;
    cudaGetSymbolAddress((void**)&xr,  g_xr);
    cudaGetSymbolAddress((void**)&wqr, g_wqkvr);
    cudaGetSymbolAddress((void**)&wor, g_wor);

    rope_tab_kernel<<<256, 256>>>();
    round_kernel<<<(M_*D_/4 + 255)/256, 256>>>((const float4*)x,    (float4*)xr,  M_*D_/4);
    round_kernel<<<(NQKV*D_/4 + 255)/256, 256>>>((const float4*)wqkv, (float4*)wqr, NQKV*D_/4);
    round_kernel<<<(D_*D_/4 + 255)/256, 256>>>((const float4*)wo,   (float4*)wor, D_*D_/4);

    gemm_tf32<true ><<<dim3(NQKV/128, M_/128), 128, GEMM_SMEM>>>(xr, wqr, pos, nullptr);
    attn_mma_kernel<<<dim3(S_/ABM, B_*H_), 256, ATTN_SMEM>>>();
    gemm_tf32<false><<<dim3(D_/128, M_/128), 128, GEMM_SMEM>>>(nullptr, wor, pos, out);
}

// round 5
// speedup vs baseline: 2.3506x; 2.3506x over previous
#include <cuda_runtime.h>
#include <cuda_fp16.h>
#include <math.h>

// Problem constants
#define B_   2
#define S_   2048
#define D_   1024
#define H_   16
#define DK_  64
#define M_   (B_*S_)     // 4096
#define NQKV (3*D_)      // 3072

// Scratch (device globals — no allocation allowed)
__device__ __half  g_Q[B_*H_*S_*DK_];             // [bh][s][d]
__device__ __half  g_K[B_*H_*S_*DK_];             // [bh][s][d]
__device__ __half  g_V[B_*H_*S_*DK_];             // [bh][d][s]  (transposed!)
__device__ __half  g_attn[(size_t)M_*D_];
__device__ __half  g_xh[(size_t)M_*D_];
__device__ __half  g_wqkvh[(size_t)NQKV*D_];
__device__ __half  g_woh[(size_t)D_*D_];
__device__ float2  g_rope[2048*32];               // [pos][pair] = (cos, sin)

// ---------------- helpers ----------------
__device__ __forceinline__ void mma_f16(float* c, const unsigned* a, const unsigned* b) {
    asm volatile(
        "mma.sync.aligned.m16n8k16.row.col.f32.f16.f16.f32 "
        "{%0,%1,%2,%3}, {%4,%5,%6,%7}, {%8,%9}, {%0,%1,%2,%3};\n"
        : "+f"(c[0]), "+f"(c[1]), "+f"(c[2]), "+f"(c[3])
        : "r"(a[0]), "r"(a[1]), "r"(a[2]), "r"(a[3]),
          "r"(b[0]), "r"(b[1]));
}

__device__ __forceinline__ void cp16(unsigned saddr, const void* gaddr) {
    asm volatile("cp.async.cg.shared.global [%0], [%1], 16;\n" :: "r"(saddr), "l"(gaddr));
}
__device__ __forceinline__ void cp_commit() { asm volatile("cp.async.commit_group;\n"); }
template<int N> __device__ __forceinline__ void cp_wait() {
    asm volatile("cp.async.wait_group %0;\n" :: "n"(N));
}
__device__ __forceinline__ unsigned pack2(float lo, float hi) {
    __half2 h = __floats2half2_rn(lo, hi);
    return *(unsigned*)&h;
}

// ---------------- fp32 -> fp16 conversion ----------------
__global__ void tohalf_kernel(const float4* __restrict__ s, uint4* __restrict__ d, int n8) {
    int i = blockIdx.x * 256 + threadIdx.x;
    if (i < n8) {
        float4 a = s[2*i], b = s[2*i+1];
        uint4 o;
        o.x = pack2(a.x, a.y); o.y = pack2(a.z, a.w);
        o.z = pack2(b.x, b.y); o.w = pack2(b.z, b.w);
        d[i] = o;
    }
}

// ---------------- RoPE cos/sin table ----------------
__global__ void rope_tab_kernel() {
    int i = blockIdx.x * 256 + threadIdx.x;     // 0..65535
    int p = i & 31, posv = i >> 5;
    float freq = exp2f(-(float)p * (13.287712379549449f / 32.0f));
    float ang = (float)posv * freq;
    float sn, cs;
    sincosf(ang, &sn, &cs);
    g_rope[i] = make_float2(cs, sn);
}

// ============================================================
// fp16 GEMM: C[m,e] = sum_k A[m,k] * W[e,k]  (K-major, K=1024)
// Block 128x128, BK=32 halves, 3-stage cp.async, 256 threads,
// 8 warps (2m x 4n), warp tile 64x32, mma m16n8k16.
// ============================================================
#define LDAH 40              // smem row stride (halves): 32 + 8 pad
#define STGH (128*LDAH)      // halves per stage per matrix = 5120

__device__ __forceinline__ void gemm_load_stage(
    __half* Asb, __half* Bsb, const __half* A, const __half* W,
    int m0, int n0, int k0, int tid)
{
    int row = tid >> 1;
    int cp  = (tid & 1) * 2;    // chunks cp, cp+1 (of 4 per 64B row)
    unsigned sa = (unsigned)__cvta_generic_to_shared(Asb + row*LDAH + cp*8);
    unsigned sb = (unsigned)__cvta_generic_to_shared(Bsb + row*LDAH + cp*8);
    const __half* ga = A + (size_t)(m0 + row)*1024 + k0 + cp*8;
    const __half* gb = W + (size_t)(n0 + row)*1024 + k0 + cp*8;
    cp16(sa,      ga);
    cp16(sa + 16, ga + 8);
    cp16(sb,      gb);
    cp16(sb + 16, gb + 8);
}

template<bool ROPE>
__global__ __launch_bounds__(256)
void gemm_f16(const __half* __restrict__ A, const __half* __restrict__ W,
              const int* __restrict__ pos, float* __restrict__ Cout)
{
    extern __shared__ __half hsm[];
    __half* As = hsm;            // 3 stages x 5120
    __half* Bs = hsm + 3*STGH;

    const int tid = threadIdx.x, lane = tid & 31, wrp = tid >> 5;
    const int wm = wrp >> 2, wn = wrp & 3;
    const int g  = lane >> 2, tg = lane & 3;
    const int m0 = blockIdx.y * 128, n0 = blockIdx.x * 128;

    float acc[4][4][4];
    #pragma unroll
    for (int i = 0; i < 4; i++)
        #pragma unroll
        for (int j = 0; j < 4; j++)
            #pragma unroll
            for (int k = 0; k < 4; k++) acc[i][j][k] = 0.f;

    gemm_load_stage(As,        Bs,        A, W, m0, n0, 0,  tid); cp_commit();
    gemm_load_stage(As + STGH, Bs + STGH, A, W, m0, n0, 32, tid); cp_commit();

    for (int kt = 0; kt < 32; kt++) {
        cp_wait<1>();
        __syncthreads();
        if (kt + 2 < 32) {
            int s = (kt + 2) % 3;
            gemm_load_stage(As + s*STGH, Bs + s*STGH, A, W, m0, n0, (kt + 2)*32, tid);
        }
        cp_commit();

        const __half* as = As + (kt % 3)*STGH;
        const __half* bs = Bs + (kt % 3)*STGH;
        #pragma unroll
        for (int ks = 0; ks < 2; ks++) {
            const int kb = ks*16 + 2*tg;
            unsigned af[4][4], bf[4][2];
            #pragma unroll
            for (int mt = 0; mt < 4; mt++) {
                int r = (wm*64 + mt*16 + g)*LDAH + kb;
                af[mt][0] = *(const unsigned*)(as + r);
                af[mt][1] = *(const unsigned*)(as + r + 8*LDAH);
                af[mt][2] = *(const unsigned*)(as + r + 8);
                af[mt][3] = *(const unsigned*)(as + r + 8*LDAH + 8);
            }
            #pragma unroll
            for (int nt = 0; nt < 4; nt++) {
                int r = (wn*32 + nt*8 + g)*LDAH + kb;
                bf[nt][0] = *(const unsigned*)(bs + r);
                bf[nt][1] = *(const unsigned*)(bs + r + 8);
            }
            #pragma unroll
            for (int mt = 0; mt < 4; mt++)
                #pragma unroll
                for (int nt = 0; nt < 4; nt++)
                    mma_f16(acc[mt][nt], af[mt], bf[nt]);
        }
    }

    // ---- epilogue ----
    if (ROPE) {
        const int baseN = n0 + wn*32;
        const int which = baseN >> 10;              // 0:Q 1:K 2:V
        const int h     = (baseN & 1023) >> 6;
        const int dd0   = baseN & 63;               // 0 or 32
        #pragma unroll
        for (int mt = 0; mt < 4; mt++) {
            int r0 = m0 + wm*64 + mt*16 + g;
            int r1 = r0 + 8;
            int b0i = r0 >> 11, s0 = r0 & 2047;
            int b1i = r1 >> 11, s1 = r1 & 2047;
            if (which == 2) {
                // transposed V: [bh][d][s]
                const size_t base0 = (size_t)(b0i*H_ + h)*DK_;
                const size_t base1 = (size_t)(b1i*H_ + h)*DK_;
                #pragma unroll
                for (int nt = 0; nt < 4; nt++) {
                    int dd = dd0 + nt*8 + 2*tg;
                    g_V[(base0 + dd    )*S_ + s0] = __float2half_rn(acc[mt][nt][0]);
                    g_V[(base0 + dd + 1)*S_ + s0] = __float2half_rn(acc[mt][nt][1]);
                    g_V[(base1 + dd    )*S_ + s1] = __float2half_rn(acc[mt][nt][2]);
                    g_V[(base1 + dd + 1)*S_ + s1] = __float2half_rn(acc[mt][nt][3]);
                }
            } else {
                __half* gq = (which == 0) ? g_Q : g_K;
                int p0 = pos[r0], p1 = pos[r1];
                __half* d0 = gq + ((size_t)((b0i*H_ + h)*S_ + s0))*DK_;
                __half* d1 = gq + ((size_t)((b1i*H_ + h)*S_ + s1))*DK_;
                #pragma unroll
                for (int nt = 0; nt < 4; nt++) {
                    int dd = dd0 + nt*8 + 2*tg;
                    int p  = dd >> 1;
                    float2 cs0 = g_rope[p0*32 + p];
                    float2 cs1 = g_rope[p1*32 + p];
                    float e0 = acc[mt][nt][0], o0 = acc[mt][nt][1];
                    float e1 = acc[mt][nt][2], o1 = acc[mt][nt][3];
                    *(unsigned*)(d0 + dd) = pack2(cs0.x*e0 - cs0.y*o0, cs0.y*e0 + cs0.x*o0);
                    *(unsigned*)(d1 + dd) = pack2(cs1.x*e1 - cs1.y*o1, cs1.y*e1 + cs1.x*o1);
                }
            }
        }
    } else {
        #pragma unroll
        for (int mt = 0; mt < 4; mt++) {
            int r0 = m0 + wm*64 + mt*16 + g;
            #pragma unroll
            for (int nt = 0; nt < 4; nt++) {
                int col = n0 + wn*32 + nt*8 + 2*tg;
                *(float2*)(Cout + (size_t)r0*1024 + col)     = make_float2(acc[mt][nt][0], acc[mt][nt][1]);
                *(float2*)(Cout + (size_t)(r0+8)*1024 + col) = make_float2(acc[mt][nt][2], acc[mt][nt][3]);
            }
        }
    }
}

// ============================================================
// Flash attention, fp16 mma m16n8k16, double-buffered cp.async.
// Block: 128 q-rows, 8 warps (16 rows each). Key tiles of 64.
// K tile [key][d] (natural), V tile [d][key] (from transposed g_V).
// ============================================================
#define ABM 128
#define ABN 64
#define KSH 72               // K/V smem row stride (halves)
#define KVSH (ABN*KSH)       // 4608 halves per matrix per stage

__device__ __forceinline__ void load_kv(__half* Kd, __half* Vd,
    const __half* Kp, const __half* Vtp, int n0, int tid)
{
    int row = tid >> 2;           // 0..63
    int ch  = (tid & 3) * 2;      // chunks ch, ch+1 (of 8 per 128B row)
    const __half* kg = Kp  + (size_t)(n0 + row)*DK_ + ch*8;
    const __half* vg = Vtp + (size_t)row*S_ + n0 + ch*8;
    unsigned ks = (unsigned)__cvta_generic_to_shared(Kd + row*KSH + ch*8);
    unsigned vs = (unsigned)__cvta_generic_to_shared(Vd + row*KSH + ch*8);
    cp16(ks,      kg);
    cp16(ks + 16, kg + 8);
    cp16(vs,      vg);
    cp16(vs + 16, vg + 8);
}

__global__ __launch_bounds__(256)
void attn_mma_kernel()
{
    extern __shared__ __half hsm[];   // 2 stages x (K 4608 + V 4608) halves

    const int tid = threadIdx.x, lane = tid & 31, w = tid >> 5;
    const int g = lane >> 2, tg = lane & 3;
    const int bh = blockIdx.y;
    const int tile = (int)gridDim.x - 1 - (int)blockIdx.x;   // heavy tiles first
    const int m0 = tile * ABM;

    const __half* Qp  = g_Q + (size_t)bh * S_ * DK_;
    const __half* Kp  = g_K + (size_t)bh * S_ * DK_;
    const __half* Vtp = g_V + (size_t)bh * DK_ * S_;

    const int row0 = m0 + w*16 + g;
    const int row1 = row0 + 8;

    // ---- Q fragments straight from gmem (one-time) ----
    unsigned qa[4][4];
    {
        const __half* q0 = Qp + (size_t)row0*DK_ + 2*tg;
        const __half* q1 = Qp + (size_t)row1*DK_ + 2*tg;
        #pragma unroll
        for (int ks = 0; ks < 4; ks++) {
            qa[ks][0] = *(const unsigned*)(q0 + ks*16);
            qa[ks][1] = *(const unsigned*)(q1 + ks*16);
            qa[ks][2] = *(const unsigned*)(q0 + ks*16 + 8);
            qa[ks][3] = *(const unsigned*)(q1 + ks*16 + 8);
        }
    }

    float o[8][4];
    #pragma unroll
    for (int nt = 0; nt < 8; nt++)
        #pragma unroll
        for (int i = 0; i < 4; i++) o[nt][i] = 0.f;

    float mrow0 = -1e30f, mrow1 = -1e30f, l0 = 0.f, l1 = 0.f;
    const int fullT = m0 / ABN;
    const int nT = fullT + 2;

    load_kv(hsm, hsm + KVSH, Kp, Vtp, 0, tid);
    cp_commit();

    for (int t = 0; t < nT; t++) {
        cp_wait<0>();
        __syncthreads();
        if (t + 1 < nT) {
            __half* st = hsm + ((t + 1) & 1) * 2 * KVSH;
            load_kv(st, st + KVSH, Kp, Vtp, (t + 1)*ABN, tid);
            cp_commit();
        }
        const __half* Ksm = hsm + (t & 1) * 2 * KVSH;
        const __half* Vsm = Ksm + KVSH;
        const int n0 = t * ABN;

        // ---- scores: S = Q @ K^T ----
        float sc[8][4];
        #pragma unroll
        for (int nt = 0; nt < 8; nt++)
            #pragma unroll
            for (int i = 0; i < 4; i++) sc[nt][i] = 0.f;

        #pragma unroll
        for (int ks = 0; ks < 4; ks++) {
            const int kb = ks*16 + 2*tg;
            #pragma unroll
            for (int nt = 0; nt < 8; nt++) {
                unsigned bf[2];
                int r = (nt*8 + g)*KSH + kb;
                bf[0] = *(const unsigned*)(Ksm + r);
                bf[1] = *(const unsigned*)(Ksm + r + 8);
                mma_f16(sc[nt], qa[ks], bf);
            }
        }

        // scale + causal mask
        if (t >= fullT) {
            #pragma unroll
            for (int nt = 0; nt < 8; nt++) {
                int c0 = n0 + nt*8 + 2*tg, c1 = c0 + 1;
                sc[nt][0] = (c0 <= row0) ? sc[nt][0]*0.125f : -1e30f;
                sc[nt][1] = (c1 <= row0) ? sc[nt][1]*0.125f : -1e30f;
                sc[nt][2] = (c0 <= row1) ? sc[nt][2]*0.125f : -1e30f;
                sc[nt][3] = (c1 <= row1) ? sc[nt][3]*0.125f : -1e30f;
            }
        } else {
            #pragma unroll
            for (int nt = 0; nt < 8; nt++)
                #pragma unroll
                for (int i = 0; i < 4; i++) sc[nt][i] *= 0.125f;
        }

        // ---- online softmax (registers + shfl) ----
        float mx0 = -1e30f, mx1 = -1e30f;
        #pragma unroll
        for (int nt = 0; nt < 8; nt++) {
            mx0 = fmaxf(mx0, fmaxf(sc[nt][0], sc[nt][1]));
            mx1 = fmaxf(mx1, fmaxf(sc[nt][2], sc[nt][3]));
        }
        mx0 = fmaxf(mx0, __shfl_xor_sync(0xffffffffu, mx0, 1));
        mx0 = fmaxf(mx0, __shfl_xor_sync(0xffffffffu, mx0, 2));
        mx1 = fmaxf(mx1, __shfl_xor_sync(0xffffffffu, mx1, 1));
        mx1 = fmaxf(mx1, __shfl_xor_sync(0xffffffffu, mx1, 2));

        float mn0 = fmaxf(mrow0, mx0), mn1 = fmaxf(mrow1, mx1);
        float al0 = __expf(mrow0 - mn0), al1 = __expf(mrow1 - mn1);
        mrow0 = mn0; mrow1 = mn1;

        float ls0 = 0.f, ls1 = 0.f;
        #pragma unroll
        for (int nt = 0; nt < 8; nt++) {
            float p0 = __expf(sc[nt][0] - mn0);
            float p1 = __expf(sc[nt][1] - mn0);
            float p2 = __expf(sc[nt][2] - mn1);
            float p3 = __expf(sc[nt][3] - mn1);
            sc[nt][0]=p0; sc[nt][1]=p1; sc[nt][2]=p2; sc[nt][3]=p3;
            ls0 += p0 + p1; ls1 += p2 + p3;
        }
        ls0 += __shfl_xor_sync(0xffffffffu, ls0, 1);
        ls0 += __shfl_xor_sync(0xffffffffu, ls0, 2);
        ls1 += __shfl_xor_sync(0xffffffffu, ls1, 1);
        ls1 += __shfl_xor_sync(0xffffffffu, ls1, 2);
        l0 = l0*al0 + ls0;
        l1 = l1*al1 + ls1;

        #pragma unroll
        for (int nt = 0; nt < 8; nt++) {
            o[nt][0] *= al0; o[nt][1] *= al0;
            o[nt][2] *= al1; o[nt][3] *= al1;
        }

        // ---- PV: O += P @ V  (P packed in-thread, V[d][key] in smem) ----
        #pragma unroll
        for (int ks = 0; ks < 4; ks++) {
            unsigned pa[4];
            pa[0] = pack2(sc[2*ks  ][0], sc[2*ks  ][1]);
            pa[1] = pack2(sc[2*ks  ][2], sc[2*ks  ][3]);
            pa[2] = pack2(sc[2*ks+1][0], sc[2*ks+1][1]);
            pa[3] = pack2(sc[2*ks+1][2], sc[2*ks+1][3]);
            const int kb = ks*16 + 2*tg;
            #pragma unroll
            for (int nt = 0; nt < 8; nt++) {
                unsigned bf[2];
                int r = (nt*8 + g)*KSH + kb;
                bf[0] = *(const unsigned*)(Vsm + r);
                bf[1] = *(const unsigned*)(Vsm + r + 8);
                mma_f16(o[nt], pa, bf);
            }
        }
    }

    // ---- epilogue: normalize + write fp16 to g_attn ----
    const float il0 = 1.0f / l0, il1 = 1.0f / l1;
    const int bb = bh >> 4, hh = bh & 15;
    __half* dst0 = g_attn + ((size_t)(bb*S_ + row0))*D_ + hh*DK_;
    __half* dst1 = g_attn + ((size_t)(bb*S_ + row1))*D_ + hh*DK_;
    #pragma unroll
    for (int nt = 0; nt < 8; nt++) {
        int d = nt*8 + 2*tg;
        *(unsigned*)(dst0 + d) = pack2(o[nt][0]*il0, o[nt][1]*il0);
        *(unsigned*)(dst1 + d) = pack2(o[nt][2]*il1, o[nt][3]*il1);
    }
}

// ============================================================
// Launch
// ============================================================
extern "C" void kernel_launch(void* const* d_in, const int* in_sizes, int n_in,
                              void* d_out, int out_size)
{
    const float* x    = (const float*)d_in[0];
    const int*   pos  = (const int*)  d_in[1];
    const float* wqkv = (const float*)d_in[2];
    const float* wo   = (const float*)d_in[3];
    float* out = (float*)d_out;

    (void)in_sizes; (void)n_in; (void)out_size;

    const int GEMM_SMEM = 3*STGH*2*(int)sizeof(__half);      // 61440
    const int ATTN_SMEM = 2*2*KVSH*(int)sizeof(__half);      // 36864
    cudaFuncSetAttribute((const void*)gemm_f16<true>,
                         cudaFuncAttributeMaxDynamicSharedMemorySize, GEMM_SMEM);
    cudaFuncSetAttribute((const void*)gemm_f16<false>,
                         cudaFuncAttributeMaxDynamicSharedMemorySize, GEMM_SMEM);
    cudaFuncSetAttribute((const void*)attn_mma_kernel,
                         cudaFuncAttributeMaxDynamicSharedMemorySize, ATTN_SMEM);

    __half* xh; __half* wqh; __half* woh; __half* ah;
    cudaGetSymbolAddress((void**)&xh,  g_xh);
    cudaGetSymbolAddress((void**)&wqh, g_wqkvh);
    cudaGetSymbolAddress((void**)&woh, g_woh);
    cudaGetSymbolAddress((void**)&ah,  g_attn);

    rope_tab_kernel<<<256, 256>>>();
    tohalf_kernel<<<(M_*D_/8 + 255)/256, 256>>>((const float4*)x,    (uint4*)xh,  M_*D_/8);
    tohalf_kernel<<<(NQKV*D_/8 + 255)/256, 256>>>((const float4*)wqkv, (uint4*)wqh, NQKV*D_/8);
    tohalf_kernel<<<(D_*D_/8 + 255)/256, 256>>>((const float4*)wo,   (uint4*)woh, D_*D_/8);

    gemm_f16<true ><<<dim3(NQKV/128, M_/128), 256, GEMM_SMEM>>>(xh, wqh, pos, nullptr);
    attn_mma_kernel<<<dim3(S_/ABM, B_*H_), 256, ATTN_SMEM>>>();
    gemm_f16<false><<<dim3(D_/128, M_/128), 256, GEMM_SMEM>>>(ah, woh, pos, out);
}

// round 6
// speedup vs baseline: 2.5789x; 1.0971x over previous
#include <cuda_runtime.h>
#include <cuda_fp16.h>
#include <math.h>

// Problem constants
#define B_   2
#define S_   2048
#define D_   1024
#define H_   16
#define DK_  64
#define M_   (B_*S_)     // 4096
#define NQKV (3*D_)      // 3072

// Scratch (device globals — no allocation allowed)
__device__ __half  g_Q[B_*H_*S_*DK_];             // [bh][s][d]
__device__ __half  g_K[B_*H_*S_*DK_];             // [bh][s][d]
__device__ __half  g_V[B_*H_*S_*DK_];             // [bh][d][s]  (transposed!)
__device__ __half  g_attn[(size_t)M_*D_];
__device__ __half  g_xh[(size_t)M_*D_];
__device__ __half  g_wqkvh[(size_t)NQKV*D_];
__device__ __half  g_woh[(size_t)D_*D_];
__device__ float2  g_rope[2048*32];               // [pos][pair] = (cos, sin)

// ---------------- helpers ----------------
__device__ __forceinline__ void mma_f16(float* c, const unsigned* a, const unsigned* b) {
    asm volatile(
        "mma.sync.aligned.m16n8k16.row.col.f32.f16.f16.f32 "
        "{%0,%1,%2,%3}, {%4,%5,%6,%7}, {%8,%9}, {%0,%1,%2,%3};\n"
        : "+f"(c[0]), "+f"(c[1]), "+f"(c[2]), "+f"(c[3])
        : "r"(a[0]), "r"(a[1]), "r"(a[2]), "r"(a[3]),
          "r"(b[0]), "r"(b[1]));
}

__device__ __forceinline__ void ldmx4(unsigned& r0, unsigned& r1, unsigned& r2, unsigned& r3,
                                      unsigned addr) {
    asm volatile("ldmatrix.sync.aligned.m8n8.x4.shared.b16 {%0,%1,%2,%3}, [%4];\n"
        : "=r"(r0), "=r"(r1), "=r"(r2), "=r"(r3) : "r"(addr));
}

__device__ __forceinline__ void cp16(unsigned saddr, const void* gaddr) {
    asm volatile("cp.async.cg.shared.global [%0], [%1], 16;\n" :: "r"(saddr), "l"(gaddr));
}
__device__ __forceinline__ void cp_commit() { asm volatile("cp.async.commit_group;\n"); }
template<int N> __device__ __forceinline__ void cp_wait() {
    asm volatile("cp.async.wait_group %0;\n" :: "n"(N));
}
__device__ __forceinline__ unsigned pack2(float lo, float hi) {
    __half2 h = __floats2half2_rn(lo, hi);
    return *(unsigned*)&h;
}

// ---------------- fp32 -> fp16 conversion ----------------
__global__ void tohalf_kernel(const float4* __restrict__ s, uint4* __restrict__ d, int n8) {
    int i = blockIdx.x * 256 + threadIdx.x;
    if (i < n8) {
        float4 a = s[2*i], b = s[2*i+1];
        uint4 o;
        o.x = pack2(a.x, a.y); o.y = pack2(a.z, a.w);
        o.z = pack2(b.x, b.y); o.w = pack2(b.z, b.w);
        d[i] = o;
    }
}

// ---------------- RoPE cos/sin table ----------------
__global__ void rope_tab_kernel() {
    int i = blockIdx.x * 256 + threadIdx.x;     // 0..65535
    int p = i & 31, posv = i >> 5;
    float freq = exp2f(-(float)p * (13.287712379549449f / 32.0f));
    float ang = (float)posv * freq;
    float sn, cs;
    sincosf(ang, &sn, &cs);
    g_rope[i] = make_float2(cs, sn);
}

// ============================================================
// fp16 GEMM: C[m,e] = sum_k A[m,k] * W[e,k]  (K-major, K=1024)
// Block 128x128, BK=32 halves, 3-stage cp.async, 256 threads,
// 8 warps (2m x 4n), warp tile 64x32, mma m16n8k16, ldmatrix.
// ============================================================
#define LDAH 40              // smem row stride (halves): 32 + 8 pad
#define STGH (128*LDAH)      // halves per stage per matrix = 5120

__device__ __forceinline__ void gemm_load_stage(
    __half* Asb, __half* Bsb, const __half* A, const __half* W,
    int m0, int n0, int k0, int tid)
{
    int row = tid >> 1;
    int cp  = (tid & 1) * 2;    // chunks cp, cp+1 (of 4 per 64B row)
    unsigned sa = (unsigned)__cvta_generic_to_shared(Asb + row*LDAH + cp*8);
    unsigned sb = (unsigned)__cvta_generic_to_shared(Bsb + row*LDAH + cp*8);
    const __half* ga = A + (size_t)(m0 + row)*1024 + k0 + cp*8;
    const __half* gb = W + (size_t)(n0 + row)*1024 + k0 + cp*8;
    cp16(sa,      ga);
    cp16(sa + 16, ga + 8);
    cp16(sb,      gb);
    cp16(sb + 16, gb + 8);
}

template<bool ROPE>
__global__ __launch_bounds__(256)
void gemm_f16(const __half* __restrict__ A, const __half* __restrict__ W,
              const int* __restrict__ pos, float* __restrict__ Cout)
{
    extern __shared__ __half hsm[];
    __half* As = hsm;            // 3 stages x 5120
    __half* Bs = hsm + 3*STGH;

    const int tid = threadIdx.x, lane = tid & 31, wrp = tid >> 5;
    const int wm = wrp >> 2, wn = wrp & 3;
    const int g  = lane >> 2, tg = lane & 3;
    const int m0 = blockIdx.y * 128, n0 = blockIdx.x * 128;

    // per-thread ldmatrix row/col offsets (in halves, within a stage)
    const int a_off = (wm*64 + (lane & 15))*LDAH + ((lane >> 4) << 3);
    const int b_off = (wn*32 + (lane & 7) + ((lane & 16) >> 1))*LDAH + (lane & 8);
    const unsigned sa_base = (unsigned)__cvta_generic_to_shared(As) + a_off*2;
    const unsigned sb_base = (unsigned)__cvta_generic_to_shared(Bs) + b_off*2;

    float acc[4][4][4];
    #pragma unroll
    for (int i = 0; i < 4; i++)
        #pragma unroll
        for (int j = 0; j < 4; j++)
            #pragma unroll
            for (int k = 0; k < 4; k++) acc[i][j][k] = 0.f;

    gemm_load_stage(As,        Bs,        A, W, m0, n0, 0,  tid); cp_commit();
    gemm_load_stage(As + STGH, Bs + STGH, A, W, m0, n0, 32, tid); cp_commit();

    for (int kt = 0; kt < 32; kt++) {
        cp_wait<1>();
        __syncthreads();
        if (kt + 2 < 32) {
            int s = (kt + 2) % 3;
            gemm_load_stage(As + s*STGH, Bs + s*STGH, A, W, m0, n0, (kt + 2)*32, tid);
        }
        cp_commit();

        const unsigned sa = sa_base + (kt % 3)*STGH*2;
        const unsigned sb = sb_base + (kt % 3)*STGH*2;
        #pragma unroll
        for (int ks = 0; ks < 2; ks++) {
            unsigned af[4][4], bf[4][2];
            #pragma unroll
            for (int mt = 0; mt < 4; mt++)
                ldmx4(af[mt][0], af[mt][1], af[mt][2], af[mt][3],
                      sa + (mt*16*LDAH + ks*16)*2);
            #pragma unroll
            for (int p = 0; p < 2; p++)
                ldmx4(bf[2*p][0], bf[2*p][1], bf[2*p+1][0], bf[2*p+1][1],
                      sb + (p*16*LDAH + ks*16)*2);
            #pragma unroll
            for (int mt = 0; mt < 4; mt++)
                #pragma unroll
                for (int nt = 0; nt < 4; nt++)
                    mma_f16(acc[mt][nt], af[mt], bf[nt]);
        }
    }

    // ---- epilogue ----
    if (ROPE) {
        const int baseN = n0 + wn*32;
        const int which = baseN >> 10;              // 0:Q 1:K 2:V
        const int h     = (baseN & 1023) >> 6;
        const int dd0   = baseN & 63;               // 0 or 32
        #pragma unroll
        for (int mt = 0; mt < 4; mt++) {
            int r0 = m0 + wm*64 + mt*16 + g;
            int r1 = r0 + 8;
            int b0i = r0 >> 11, s0 = r0 & 2047;
            int b1i = r1 >> 11, s1 = r1 & 2047;
            if (which == 2) {
                // transposed V: [bh][d][s]
                const size_t base0 = (size_t)(b0i*H_ + h)*DK_;
                const size_t base1 = (size_t)(b1i*H_ + h)*DK_;
                #pragma unroll
                for (int nt = 0; nt < 4; nt++) {
                    int dd = dd0 + nt*8 + 2*tg;
                    g_V[(base0 + dd    )*S_ + s0] = __float2half_rn(acc[mt][nt][0]);
                    g_V[(base0 + dd + 1)*S_ + s0] = __float2half_rn(acc[mt][nt][1]);
                    g_V[(base1 + dd    )*S_ + s1] = __float2half_rn(acc[mt][nt][2]);
                    g_V[(base1 + dd + 1)*S_ + s1] = __float2half_rn(acc[mt][nt][3]);
                }
            } else {
                __half* gq = (which == 0) ? g_Q : g_K;
                int p0 = pos[r0], p1 = pos[r1];
                __half* d0 = gq + ((size_t)((b0i*H_ + h)*S_ + s0))*DK_;
                __half* d1 = gq + ((size_t)((b1i*H_ + h)*S_ + s1))*DK_;
                #pragma unroll
                for (int nt = 0; nt < 4; nt++) {
                    int dd = dd0 + nt*8 + 2*tg;
                    int p  = dd >> 1;
                    float2 cs0 = g_rope[p0*32 + p];
                    float2 cs1 = g_rope[p1*32 + p];
                    float e0 = acc[mt][nt][0], o0 = acc[mt][nt][1];
                    float e1 = acc[mt][nt][2], o1 = acc[mt][nt][3];
                    *(unsigned*)(d0 + dd) = pack2(cs0.x*e0 - cs0.y*o0, cs0.y*e0 + cs0.x*o0);
                    *(unsigned*)(d1 + dd) = pack2(cs1.x*e1 - cs1.y*o1, cs1.y*e1 + cs1.x*o1);
                }
            }
        }
    } else {
        #pragma unroll
        for (int mt = 0; mt < 4; mt++) {
            int r0 = m0 + wm*64 + mt*16 + g;
            #pragma unroll
            for (int nt = 0; nt < 4; nt++) {
                int col = n0 + wn*32 + nt*8 + 2*tg;
                *(float2*)(Cout + (size_t)r0*1024 + col)     = make_float2(acc[mt][nt][0], acc[mt][nt][1]);
                *(float2*)(Cout + (size_t)(r0+8)*1024 + col) = make_float2(acc[mt][nt][2], acc[mt][nt][3]);
            }
        }
    }
}

// ============================================================
// Flash attention, fp16 mma m16n8k16, double-buffered cp.async,
// ldmatrix fragment loads.
// Block: 128 q-rows, 8 warps (16 rows each). Key tiles of 64.
// K tile [key][d] (natural), V tile [d][key] (from transposed g_V).
// ============================================================
#define ABM 128
#define ABN 64
#define KSH 72               // K/V smem row stride (halves)
#define KVSH (ABN*KSH)       // 4608 halves per matrix per stage

__device__ __forceinline__ void load_kv(__half* Kd, __half* Vd,
    const __half* Kp, const __half* Vtp, int n0, int tid)
{
    int row = tid >> 2;           // 0..63
    int ch  = (tid & 3) * 2;      // chunks ch, ch+1 (of 8 per 128B row)
    const __half* kg = Kp  + (size_t)(n0 + row)*DK_ + ch*8;
    const __half* vg = Vtp + (size_t)row*S_ + n0 + ch*8;
    unsigned ks = (unsigned)__cvta_generic_to_shared(Kd + row*KSH + ch*8);
    unsigned vs = (unsigned)__cvta_generic_to_shared(Vd + row*KSH + ch*8);
    cp16(ks,      kg);
    cp16(ks + 16, kg + 8);
    cp16(vs,      vg);
    cp16(vs + 16, vg + 8);
}

__global__ __launch_bounds__(256)
void attn_mma_kernel()
{
    extern __shared__ __half hsm[];   // 2 stages x (K 4608 + V 4608) halves

    const int tid = threadIdx.x, lane = tid & 31, w = tid >> 5;
    const int g = lane >> 2, tg = lane & 3;
    const int bh = blockIdx.y;
    const int tile = (int)gridDim.x - 1 - (int)blockIdx.x;   // heavy tiles first
    const int m0 = tile * ABM;

    const __half* Qp  = g_Q + (size_t)bh * S_ * DK_;
    const __half* Kp  = g_K + (size_t)bh * S_ * DK_;
    const __half* Vtp = g_V + (size_t)bh * DK_ * S_;

    const int row0 = m0 + w*16 + g;
    const int row1 = row0 + 8;

    // ldmatrix row offset (same pattern for K and V tiles)
    const int kv_off = ((lane & 7) + ((lane & 16) >> 1))*KSH + (lane & 8);
    const unsigned smem_base = (unsigned)__cvta_generic_to_shared(hsm) + kv_off*2;

    // ---- Q fragments straight from gmem (one-time) ----
    unsigned qa[4][4];
    {
        const __half* q0 = Qp + (size_t)row0*DK_ + 2*tg;
        const __half* q1 = Qp + (size_t)row1*DK_ + 2*tg;
        #pragma unroll
        for (int ks = 0; ks < 4; ks++) {
            qa[ks][0] = *(const unsigned*)(q0 + ks*16);
            qa[ks][1] = *(const unsigned*)(q1 + ks*16);
            qa[ks][2] = *(const unsigned*)(q0 + ks*16 + 8);
            qa[ks][3] = *(const unsigned*)(q1 + ks*16 + 8);
        }
    }

    float o[8][4];
    #pragma unroll
    for (int nt = 0; nt < 8; nt++)
        #pragma unroll
        for (int i = 0; i < 4; i++) o[nt][i] = 0.f;

    float mrow0 = -1e30f, mrow1 = -1e30f, l0 = 0.f, l1 = 0.f;
    const int fullT = m0 / ABN;
    const int nT = fullT + 2;

    load_kv(hsm, hsm + KVSH, Kp, Vtp, 0, tid);
    cp_commit();

    for (int t = 0; t < nT; t++) {
        cp_wait<0>();
        __syncthreads();
        if (t + 1 < nT) {
            __half* st = hsm + ((t + 1) & 1) * 2 * KVSH;
            load_kv(st, st + KVSH, Kp, Vtp, (t + 1)*ABN, tid);
            cp_commit();
        }
        const unsigned Ksb = smem_base + ((t & 1) * 2 * KVSH)*2;
        const unsigned Vsb = Ksb + KVSH*2;
        const int n0 = t * ABN;

        // ---- scores: S = Q @ K^T ----
        float sc[8][4];
        #pragma unroll
        for (int nt = 0; nt < 8; nt++)
            #pragma unroll
            for (int i = 0; i < 4; i++) sc[nt][i] = 0.f;

        #pragma unroll
        for (int ks = 0; ks < 4; ks++) {
            #pragma unroll
            for (int p = 0; p < 4; p++) {
                unsigned bf[2][2];
                ldmx4(bf[0][0], bf[0][1], bf[1][0], bf[1][1],
                      Ksb + (p*16*KSH + ks*16)*2);
                mma_f16(sc[2*p],   qa[ks], bf[0]);
                mma_f16(sc[2*p+1], qa[ks], bf[1]);
            }
        }

        // scale + causal mask
        if (t >= fullT) {
            #pragma unroll
            for (int nt = 0; nt < 8; nt++) {
                int c0 = n0 + nt*8 + 2*tg, c1 = c0 + 1;
                sc[nt][0] = (c0 <= row0) ? sc[nt][0]*0.125f : -1e30f;
                sc[nt][1] = (c1 <= row0) ? sc[nt][1]*0.125f : -1e30f;
                sc[nt][2] = (c0 <= row1) ? sc[nt][2]*0.125f : -1e30f;
                sc[nt][3] = (c1 <= row1) ? sc[nt][3]*0.125f : -1e30f;
            }
        } else {
            #pragma unroll
            for (int nt = 0; nt < 8; nt++)
                #pragma unroll
                for (int i = 0; i < 4; i++) sc[nt][i] *= 0.125f;
        }

        // ---- online softmax (registers + shfl) ----
        float mx0 = -1e30f, mx1 = -1e30f;
        #pragma unroll
        for (int nt = 0; nt < 8; nt++) {
            mx0 = fmaxf(mx0, fmaxf(sc[nt][0], sc[nt][1]));
            mx1 = fmaxf(mx1, fmaxf(sc[nt][2], sc[nt][3]));
        }
        mx0 = fmaxf(mx0, __shfl_xor_sync(0xffffffffu, mx0, 1));
        mx0 = fmaxf(mx0, __shfl_xor_sync(0xffffffffu, mx0, 2));
        mx1 = fmaxf(mx1, __shfl_xor_sync(0xffffffffu, mx1, 1));
        mx1 = fmaxf(mx1, __shfl_xor_sync(0xffffffffu, mx1, 2));

        float mn0 = fmaxf(mrow0, mx0), mn1 = fmaxf(mrow1, mx1);
        float al0 = __expf(mrow0 - mn0), al1 = __expf(mrow1 - mn1);
        mrow0 = mn0; mrow1 = mn1;

        float ls0 = 0.f, ls1 = 0.f;
        #pragma unroll
        for (int nt = 0; nt < 8; nt++) {
            float p0 = __expf(sc[nt][0] - mn0);
            float p1 = __expf(sc[nt][1] - mn0);
            float p2 = __expf(sc[nt][2] - mn1);
            float p3 = __expf(sc[nt][3] - mn1);
            sc[nt][0]=p0; sc[nt][1]=p1; sc[nt][2]=p2; sc[nt][3]=p3;
            ls0 += p0 + p1; ls1 += p2 + p3;
        }
        ls0 += __shfl_xor_sync(0xffffffffu, ls0, 1);
        ls0 += __shfl_xor_sync(0xffffffffu, ls0, 2);
        ls1 += __shfl_xor_sync(0xffffffffu, ls1, 1);
        ls1 += __shfl_xor_sync(0xffffffffu, ls1, 2);
        l0 = l0*al0 + ls0;
        l1 = l1*al1 + ls1;

        #pragma unroll
        for (int nt = 0; nt < 8; nt++) {
            o[nt][0] *= al0; o[nt][1] *= al0;
            o[nt][2] *= al1; o[nt][3] *= al1;
        }

        // ---- PV: O += P @ V  (P packed in-thread, V[d][key] in smem) ----
        #pragma unroll
        for (int ks = 0; ks < 4; ks++) {
            unsigned pa[4];
            pa[0] = pack2(sc[2*ks  ][0], sc[2*ks  ][1]);
            pa[1] = pack2(sc[2*ks  ][2], sc[2*ks  ][3]);
            pa[2] = pack2(sc[2*ks+1][0], sc[2*ks+1][1]);
            pa[3] = pack2(sc[2*ks+1][2], sc[2*ks+1][3]);
            #pragma unroll
            for (int p = 0; p < 4; p++) {
                unsigned bf[2][2];
                ldmx4(bf[0][0], bf[0][1], bf[1][0], bf[1][1],
                      Vsb + (p*16*KSH + ks*16)*2);
                mma_f16(o[2*p],   pa, bf[0]);
                mma_f16(o[2*p+1], pa, bf[1]);
            }
        }
    }

    // ---- epilogue: normalize + write fp16 to g_attn ----
    const float il0 = 1.0f / l0, il1 = 1.0f / l1;
    const int bb = bh >> 4, hh = bh & 15;
    __half* dst0 = g_attn + ((size_t)(bb*S_ + row0))*D_ + hh*DK_;
    __half* dst1 = g_attn + ((size_t)(bb*S_ + row1))*D_ + hh*DK_;
    #pragma unroll
    for (int nt = 0; nt < 8; nt++) {
        int d = nt*8 + 2*tg;
        *(unsigned*)(dst0 + d) = pack2(o[nt][0]*il0, o[nt][1]*il0);
        *(unsigned*)(dst1 + d) = pack2(o[nt][2]*il1, o[nt][3]*il1);
    }
}

// ============================================================
// Launch
// ============================================================
extern "C" void kernel_launch(void* const* d_in, const int* in_sizes, int n_in,
                              void* d_out, int out_size)
{
    const float* x    = (const float*)d_in[0];
    const int*   pos  = (const int*)  d_in[1];
    const float* wqkv = (const float*)d_in[2];
    const float* wo   = (const float*)d_in[3];
    float* out = (float*)d_out;

    (void)in_sizes; (void)n_in; (void)out_size;

    const int GEMM_SMEM = 3*STGH*2*(int)sizeof(__half);      // 61440
    const int ATTN_SMEM = 2*2*KVSH*(int)sizeof(__half);      // 36864
    cudaFuncSetAttribute((const void*)gemm_f16<true>,
                         cudaFuncAttributeMaxDynamicSharedMemorySize, GEMM_SMEM);
    cudaFuncSetAttribute((const void*)gemm_f16<false>,
                         cudaFuncAttributeMaxDynamicSharedMemorySize, GEMM_SMEM);
    cudaFuncSetAttribute((const void*)attn_mma_kernel,
                         cudaFuncAttributeMaxDynamicSharedMemorySize, ATTN_SMEM);

    __half* xh; __half* wqh; __half* woh; __half* ah;
    cudaGetSymbolAddress((void**)&xh,  g_xh);
    cudaGetSymbolAddress((void**)&wqh, g_wqkvh);
    cudaGetSymbolAddress((void**)&woh, g_woh);
    cudaGetSymbolAddress((void**)&ah,  g_attn);

    rope_tab_kernel<<<256, 256>>>();
    tohalf_kernel<<<(M_*D_/8 + 255)/256, 256>>>((const float4*)x,    (uint4*)xh,  M_*D_/8);
    tohalf_kernel<<<(NQKV*D_/8 + 255)/256, 256>>>((const float4*)wqkv, (uint4*)wqh, NQKV*D_/8);
    tohalf_kernel<<<(D_*D_/8 + 255)/256, 256>>>((const float4*)wo,   (uint4*)woh, D_*D_/8);

    gemm_f16<true ><<<dim3(NQKV/128, M_/128), 256, GEMM_SMEM>>>(xh, wqh, pos, nullptr);
    attn_mma_kernel<<<dim3(S_/ABM, B_*H_), 256, ATTN_SMEM>>>();
    gemm_f16<false><<<dim3(D_/128, M_/128), 256, GEMM_SMEM>>>(ah, woh, pos, out);
}